// round 1
// baseline (speedup 1.0000x reference)
#include <cuda_runtime.h>
#include <cuda_bf16.h>
#include <cub/cub.cuh>

// ---------------- problem constants ----------------
#define HH 200
#define WW 200
#define NPIX (HH * WW)          // 40000
#define NANCH 360000            // HH*WW*9
#define PRE_NMS 6000
#define POST_NMS 300
#define NBLK 94                 // ceil(6000/64)
#define CLS_OFF 0
#define LOC_OFF 720000
#define ROI_OFF 2160000

// ---------------- scratch (static device allocations) ----------------
__device__ float g_x[512 * NPIX];                       // relu(conv1) output, [oc][y][x]
__device__ float g_boxes[NANCH * 4];
__device__ float g_score[NANCH];
__device__ unsigned long long g_keys[NANCH];
__device__ unsigned long long g_keys_sorted[NANCH];
__device__ float g_top[PRE_NMS * 4];
__device__ int g_validtop[PRE_NMS];
__device__ unsigned long long g_mask[(size_t)PRE_NMS * NBLK];
__device__ int g_kept[POST_NMS];
__device__ unsigned char g_cub_temp[64u << 20];

// ---------------- conv1: 3x3 512->512, pad 1, relu ----------------
// Tile: 64 oc x 64 px (8x8 spatial). 256 threads, each 4 oc x 4 px.
__global__ __launch_bounds__(256) void conv1_kernel(
    const float* __restrict__ feat, const float* __restrict__ w1,
    const float* __restrict__ b1) {
  __shared__ float As[64][73];      // [oc][k], k = ic*9 + kh*3 + kw (pad 73: read/write conflict-free)
  __shared__ float Bs[8][10][11];   // [ic][y][x], stride 11 keeps reads conflict-free

  const int tid = threadIdx.x;
  const int i = tid & 15;           // px group (0..15), 4 px each
  const int j = tid >> 4;           // oc group (0..15), 4 oc each
  const int bx = blockIdx.x;        // 0..24
  const int by = blockIdx.y;        // 0..24
  const int oc0 = blockIdx.z * 64;

  const int r = i >> 1;             // row within 8x8 tile
  const int c0 = (i & 1) * 4;       // col start within row

  float acc[4][4];
#pragma unroll
  for (int m = 0; m < 4; m++)
#pragma unroll
    for (int p = 0; p < 4; p++) acc[m][p] = 0.f;

  const int y0 = by * 8 - 1;
  const int x0 = bx * 8 - 1;

  // A-load mapping: tid -> (oc = tid/4, k0 = (tid%4)*18), 18 consecutive k (coalesced 72B runs)
  const int a_oc = tid >> 2;
  const int a_k0 = (tid & 3) * 18;

  for (int ic0 = 0; ic0 < 512; ic0 += 8) {
    {
      const float* wp = w1 + (size_t)(oc0 + a_oc) * 4608 + (size_t)ic0 * 9 + a_k0;
#pragma unroll
      for (int t = 0; t < 18; t++) As[a_oc][a_k0 + t] = wp[t];
    }
    for (int idx = tid; idx < 800; idx += 256) {
      int ic = idx / 100;
      int rem = idx - ic * 100;
      int yy = rem / 10, xx = rem - yy * 10;
      int y = y0 + yy, x = x0 + xx;
      float v = 0.f;
      if ((unsigned)y < (unsigned)HH && (unsigned)x < (unsigned)WW)
        v = feat[(size_t)(ic0 + ic) * NPIX + y * WW + x];
      Bs[ic][yy][xx] = v;
    }
    __syncthreads();

#pragma unroll
    for (int ic = 0; ic < 8; ic++) {
#pragma unroll
      for (int kh = 0; kh < 3; kh++) {
#pragma unroll
        for (int kw = 0; kw < 3; kw++) {
          const int k = ic * 9 + kh * 3 + kw;
          float a0 = As[j * 4 + 0][k];
          float a1 = As[j * 4 + 1][k];
          float a2 = As[j * 4 + 2][k];
          float a3 = As[j * 4 + 3][k];
          float bv0 = Bs[ic][r + kh][c0 + kw + 0];
          float bv1 = Bs[ic][r + kh][c0 + kw + 1];
          float bv2 = Bs[ic][r + kh][c0 + kw + 2];
          float bv3 = Bs[ic][r + kh][c0 + kw + 3];
          acc[0][0] += a0 * bv0; acc[0][1] += a0 * bv1; acc[0][2] += a0 * bv2; acc[0][3] += a0 * bv3;
          acc[1][0] += a1 * bv0; acc[1][1] += a1 * bv1; acc[1][2] += a1 * bv2; acc[1][3] += a1 * bv3;
          acc[2][0] += a2 * bv0; acc[2][1] += a2 * bv1; acc[2][2] += a2 * bv2; acc[2][3] += a2 * bv3;
          acc[3][0] += a3 * bv0; acc[3][1] += a3 * bv1; acc[3][2] += a3 * bv2; acc[3][3] += a3 * bv3;
        }
      }
    }
    __syncthreads();
  }

#pragma unroll
  for (int m = 0; m < 4; m++) {
    const int oc = oc0 + j * 4 + m;
    const float bias = b1[oc];
#pragma unroll
    for (int p = 0; p < 4; p++) {
      const int px = i * 4 + p;
      const int y = by * 8 + (px >> 3);
      const int x = bx * 8 + (px & 7);
      float v = acc[m][p] + bias;
      v = v > 0.f ? v : 0.f;
      g_x[(size_t)oc * NPIX + y * WW + x] = v;
    }
  }
}

// ---------------- head: fused 1x1 convs (18 cls + 36 loc), writes transposed into d_out ----------------
__global__ __launch_bounds__(160) void head_kernel(
    const float* __restrict__ wc, const float* __restrict__ bc,
    const float* __restrict__ wl, const float* __restrict__ bl,
    float* __restrict__ out) {
  __shared__ float Xs[32][160];
  __shared__ float Ws[32][54];
  const int tid = threadIdx.x;
  const int px0 = blockIdx.x * 160;

  float acc[54];
#pragma unroll
  for (int o = 0; o < 54; o++) acc[o] = 0.f;

  for (int ic0 = 0; ic0 < 512; ic0 += 32) {
#pragma unroll
    for (int t = 0; t < 32; t++)
      Xs[t][tid] = g_x[(size_t)(ic0 + t) * NPIX + px0 + tid];
    for (int idx = tid; idx < 32 * 54; idx += 160) {
      int ic = idx / 54;
      int o = idx - ic * 54;
      float w = (o < 18) ? wc[o * 512 + ic0 + ic] : wl[(o - 18) * 512 + ic0 + ic];
      Ws[ic][o] = w;
    }
    __syncthreads();
#pragma unroll 4
    for (int ic = 0; ic < 32; ic++) {
      float xv = Xs[ic][tid];
#pragma unroll
      for (int o = 0; o < 54; o++) acc[o] += Ws[ic][o] * xv;
    }
    __syncthreads();
  }

  const int px = px0 + tid;
#pragma unroll
  for (int o = 0; o < 54; o++) {
    float v;
    if (o < 18) {
      v = acc[o] + bc[o];
      int a = o >> 1, cc = o & 1;
      out[CLS_OFF + ((size_t)px * 9 + a) * 2 + cc] = v;
    } else {
      int l = o - 18;
      v = acc[o] + bl[l];
      int a = l >> 2, cc = l & 3;
      out[LOC_OFF + ((size_t)px * 9 + a) * 4 + cc] = v;
    }
  }
}

// ---------------- decode + score + sort key ----------------
__global__ void decode_kernel(const float* __restrict__ anchor,
                              const float* __restrict__ out) {
  const int n = blockIdx.x * 256 + threadIdx.x;
  if (n >= NANCH) return;

  const float ax1 = anchor[(size_t)n * 4 + 0];
  const float ay1 = anchor[(size_t)n * 4 + 1];
  const float ax2 = anchor[(size_t)n * 4 + 2];
  const float ay2 = anchor[(size_t)n * 4 + 3];
  const float acx = __fmul_rn(__fadd_rn(ax2, ax1), 0.5f);
  const float acy = __fmul_rn(__fadd_rn(ay2, ay1), 0.5f);
  const float aw = __fsub_rn(ax2, ax1);
  const float ah = __fsub_rn(ay2, ay1);

  const float l0 = out[LOC_OFF + (size_t)n * 4 + 0];
  const float l1 = out[LOC_OFF + (size_t)n * 4 + 1];
  const float l2 = out[LOC_OFF + (size_t)n * 4 + 2];
  const float l3 = out[LOC_OFF + (size_t)n * 4 + 3];

  const float cx = __fadd_rn(__fmul_rn(l0, aw), acx);
  const float cy = __fadd_rn(__fmul_rn(l1, ah), acy);
  const float w = __fmul_rn(expf(l2), aw);
  const float h = __fmul_rn(expf(l3), ah);

  float x1 = __fsub_rn(cx, __fmul_rn(w, 0.5f));
  float y1 = __fsub_rn(cy, __fmul_rn(h, 0.5f));
  float x2 = __fadd_rn(cx, __fmul_rn(w, 0.5f));
  float y2 = __fadd_rn(cy, __fmul_rn(h, 0.5f));
  x1 = fminf(fmaxf(x1, 0.f), 1.f);
  y1 = fminf(fmaxf(y1, 0.f), 1.f);
  x2 = fminf(fmaxf(x2, 0.f), 1.f);
  y2 = fminf(fmaxf(y2, 0.f), 1.f);

  g_boxes[(size_t)n * 4 + 0] = x1;
  g_boxes[(size_t)n * 4 + 1] = y1;
  g_boxes[(size_t)n * 4 + 2] = x2;
  g_boxes[(size_t)n * 4 + 3] = y2;

  const float c0v = out[CLS_OFF + (size_t)n * 2 + 0];
  const float c1v = out[CLS_OFF + (size_t)n * 2 + 1];
  float s = 1.f / (1.f + expf(__fsub_rn(c0v, c1v)));

  const float MINSZ = (float)(16.0 / 1000.0);
  const float ws = __fsub_rn(x2, x1);
  const float hs = __fsub_rn(y2, y1);
  const bool valid = (hs >= MINSZ) && (ws >= MINSZ);
  if (!valid) s = -1.0f;
  g_score[n] = s;

  unsigned int bits = __float_as_uint(s);
  unsigned int u = (bits & 0x80000000u) ? ~bits : (bits | 0x80000000u);
  // ascending sort -> descending score, ties ascending index (matches jax top_k)
  g_keys[n] = ((unsigned long long)(~u) << 32) | (unsigned int)n;
}

// ---------------- gather top 6000 ----------------
__global__ void gather_kernel() {
  const int i = blockIdx.x * 256 + threadIdx.x;
  if (i >= PRE_NMS) return;
  const unsigned long long k = g_keys_sorted[i];
  const int idx = (int)(k & 0xffffffffu);
  g_top[i * 4 + 0] = g_boxes[(size_t)idx * 4 + 0];
  g_top[i * 4 + 1] = g_boxes[(size_t)idx * 4 + 1];
  g_top[i * 4 + 2] = g_boxes[(size_t)idx * 4 + 2];
  g_top[i * 4 + 3] = g_boxes[(size_t)idx * 4 + 3];
  g_validtop[i] = (g_score[idx] >= 0.f) ? 1 : 0;
}

// ---------------- NMS bitmask ----------------
__global__ __launch_bounds__(64) void mask_kernel() {
  const int cb = blockIdx.x;
  const int rb = blockIdx.y;
  __shared__ float cbx[64][4];
  const int t = threadIdx.x;
  const int jg = cb * 64 + t;
  if (jg < PRE_NMS) {
    cbx[t][0] = g_top[jg * 4 + 0];
    cbx[t][1] = g_top[jg * 4 + 1];
    cbx[t][2] = g_top[jg * 4 + 2];
    cbx[t][3] = g_top[jg * 4 + 3];
  }
  __syncthreads();
  const int i = rb * 64 + t;
  if (i >= PRE_NMS) return;

  const float ix1 = g_top[i * 4 + 0];
  const float iy1 = g_top[i * 4 + 1];
  const float ix2 = g_top[i * 4 + 2];
  const float iy2 = g_top[i * 4 + 3];
  const float area_i = __fmul_rn(__fsub_rn(ix2, ix1), __fsub_rn(iy2, iy1));

  unsigned long long bits = 0ull;
  const int jmax = min(64, PRE_NMS - cb * 64);
  for (int jj = 0; jj < jmax; jj++) {
    const int j = cb * 64 + jj;
    if (j <= i) continue;
    const float bx1 = cbx[jj][0], by1 = cbx[jj][1], bx2 = cbx[jj][2], by2 = cbx[jj][3];
    const float area_j = __fmul_rn(__fsub_rn(bx2, bx1), __fsub_rn(by2, by1));
    const float xx1 = fmaxf(ix1, bx1);
    const float yy1 = fmaxf(iy1, by1);
    const float xx2 = fminf(ix2, bx2);
    const float yy2 = fminf(iy2, by2);
    const float iw = fmaxf(__fsub_rn(xx2, xx1), 0.f);
    const float ih = fmaxf(__fsub_rn(yy2, yy1), 0.f);
    const float inter = __fmul_rn(iw, ih);
    const float denom = __fadd_rn(__fsub_rn(__fadd_rn(area_i, area_j), inter), 1e-12f);
    const float iou = inter / denom;
    if (iou > 0.7f) bits |= (1ull << jj);
  }
  g_mask[(size_t)i * NBLK + cb] = bits;
}

// ---------------- sequential keep (1 warp) + rois write, early exit at 300 ----------------
__global__ void keep_kernel(float* __restrict__ out) {
  const int lane = threadIdx.x;
  unsigned long long r0 = 0ull, r1 = 0ull, r2 = 0ull;  // words lane, lane+32, lane+64
  __shared__ int kept_s[POST_NMS];
  int count = 0;

  for (int i = 0; i < PRE_NMS; i++) {
    const int w = i >> 6;
    const int b = i & 63;
    const int slot = w >> 5;
    const int src = w & 31;
    unsigned long long v = (slot == 0) ? r0 : ((slot == 1) ? r1 : r2);
    unsigned long long wv = __shfl_sync(0xffffffffu, v, src);
    const bool alive = g_validtop[i] && !((wv >> b) & 1ull);
    if (alive) {
      const unsigned long long* row = &g_mask[(size_t)i * NBLK];
      r0 |= row[lane];
      r1 |= row[lane + 32];
      if (lane + 64 < NBLK) r2 |= row[lane + 64];
      if (lane == 0) kept_s[count] = i;
      count++;
      if (count == POST_NMS) break;
    }
  }
  __syncwarp();

  for (int k = lane; k < POST_NMS; k += 32) {
    float b0 = 0.f, b1v = 0.f, b2 = 0.f, b3 = 0.f;
    if (k < count) {
      const int i = kept_s[k];
      b0 = g_top[i * 4 + 0];
      b1v = g_top[i * 4 + 1];
      b2 = g_top[i * 4 + 2];
      b3 = g_top[i * 4 + 3];
    }
    out[ROI_OFF + k * 4 + 0] = b0;
    out[ROI_OFF + k * 4 + 1] = b1v;
    out[ROI_OFF + k * 4 + 2] = b2;
    out[ROI_OFF + k * 4 + 3] = b3;
  }
}

// ---------------- launch ----------------
extern "C" void kernel_launch(void* const* d_in, const int* in_sizes, int n_in,
                              void* d_out, int out_size) {
  const float* feat = (const float*)d_in[0];
  const float* anchor = (const float*)d_in[1];
  const float* w1 = (const float*)d_in[2];
  const float* b1 = (const float*)d_in[3];
  const float* wc = (const float*)d_in[4];
  const float* bc = (const float*)d_in[5];
  const float* wl = (const float*)d_in[6];
  const float* bl = (const float*)d_in[7];
  float* out = (float*)d_out;

  conv1_kernel<<<dim3(25, 25, 8), 256>>>(feat, w1, b1);
  head_kernel<<<250, 160>>>(wc, bc, wl, bl, out);
  decode_kernel<<<(NANCH + 255) / 256, 256>>>(anchor, out);

  // CUB radix sort on 64-bit keys (static temp storage; kernel launches only -> capturable)
  void* d_temp = nullptr;
  unsigned long long* dk = nullptr;
  unsigned long long* dks = nullptr;
  cudaGetSymbolAddress(&d_temp, g_cub_temp);
  cudaGetSymbolAddress((void**)&dk, g_keys);
  cudaGetSymbolAddress((void**)&dks, g_keys_sorted);
  size_t temp_bytes = 0;
  cub::DeviceRadixSort::SortKeys(nullptr, temp_bytes, dk, dks, NANCH, 0, 64,
                                 (cudaStream_t)0);
  if (temp_bytes > (size_t)(64u << 20)) temp_bytes = (size_t)(64u << 20);
  cub::DeviceRadixSort::SortKeys(d_temp, temp_bytes, dk, dks, NANCH, 0, 64,
                                 (cudaStream_t)0);

  gather_kernel<<<(PRE_NMS + 255) / 256, 256>>>();
  mask_kernel<<<dim3(NBLK, NBLK), 64>>>();
  keep_kernel<<<1, 32>>>(out);
}

// round 2
// speedup vs baseline: 1.0013x; 1.0013x over previous
#include <cuda_runtime.h>
#include <cuda_bf16.h>
#include <cub/cub.cuh>

// ---------------- problem constants ----------------
#define HH 200
#define WW 200
#define NPIX (HH * WW)          // 40000
#define NANCH 360000            // HH*WW*9
#define PRE_NMS 6000
#define POST_NMS 300
#define NBLK 94                 // ceil(6000/64)
#define CLS_OFF 0
#define LOC_OFF 720000
#define ROI_OFF 2160000

// ---------------- scratch (static device allocations) ----------------
__device__ float g_x[512 * NPIX];                       // relu(conv1) output, [oc][y][x]
__device__ float g_boxes[NANCH * 4];
__device__ float g_score[NANCH];
__device__ unsigned long long g_keys[NANCH];
__device__ unsigned long long g_keys_sorted[NANCH];
__device__ float g_top[PRE_NMS * 4];
__device__ int g_validtop[PRE_NMS];
__device__ unsigned long long g_mask[(size_t)PRE_NMS * NBLK];
__device__ int g_kept[POST_NMS];
__device__ unsigned char g_cub_temp[64u << 20];

// ---------------- conv1: 3x3 512->512, pad 1, relu ----------------
// Tile: 64 oc x 64 px (8x8 spatial). 256 threads, each 4 oc x 4 px.
__global__ __launch_bounds__(256) void conv1_kernel(
    const float* __restrict__ feat, const float* __restrict__ w1,
    const float* __restrict__ b1) {
  __shared__ float As[64][73];      // [oc][k], k = ic*9 + kh*3 + kw (pad 73: read/write conflict-free)
  __shared__ float Bs[8][10][11];   // [ic][y][x], stride 11 keeps reads conflict-free

  const int tid = threadIdx.x;
  const int i = tid & 15;           // px group (0..15), 4 px each
  const int j = tid >> 4;           // oc group (0..15), 4 oc each
  const int bx = blockIdx.x;        // 0..24
  const int by = blockIdx.y;        // 0..24
  const int oc0 = blockIdx.z * 64;

  const int r = i >> 1;             // row within 8x8 tile
  const int c0 = (i & 1) * 4;       // col start within row

  float acc[4][4];
#pragma unroll
  for (int m = 0; m < 4; m++)
#pragma unroll
    for (int p = 0; p < 4; p++) acc[m][p] = 0.f;

  const int y0 = by * 8 - 1;
  const int x0 = bx * 8 - 1;

  // A-load mapping: tid -> (oc = tid/4, k0 = (tid%4)*18), 18 consecutive k (coalesced 72B runs)
  const int a_oc = tid >> 2;
  const int a_k0 = (tid & 3) * 18;

  for (int ic0 = 0; ic0 < 512; ic0 += 8) {
    {
      const float* wp = w1 + (size_t)(oc0 + a_oc) * 4608 + (size_t)ic0 * 9 + a_k0;
#pragma unroll
      for (int t = 0; t < 18; t++) As[a_oc][a_k0 + t] = wp[t];
    }
    for (int idx = tid; idx < 800; idx += 256) {
      int ic = idx / 100;
      int rem = idx - ic * 100;
      int yy = rem / 10, xx = rem - yy * 10;
      int y = y0 + yy, x = x0 + xx;
      float v = 0.f;
      if ((unsigned)y < (unsigned)HH && (unsigned)x < (unsigned)WW)
        v = feat[(size_t)(ic0 + ic) * NPIX + y * WW + x];
      Bs[ic][yy][xx] = v;
    }
    __syncthreads();

#pragma unroll
    for (int ic = 0; ic < 8; ic++) {
#pragma unroll
      for (int kh = 0; kh < 3; kh++) {
#pragma unroll
        for (int kw = 0; kw < 3; kw++) {
          const int k = ic * 9 + kh * 3 + kw;
          float a0 = As[j * 4 + 0][k];
          float a1 = As[j * 4 + 1][k];
          float a2 = As[j * 4 + 2][k];
          float a3 = As[j * 4 + 3][k];
          float bv0 = Bs[ic][r + kh][c0 + kw + 0];
          float bv1 = Bs[ic][r + kh][c0 + kw + 1];
          float bv2 = Bs[ic][r + kh][c0 + kw + 2];
          float bv3 = Bs[ic][r + kh][c0 + kw + 3];
          acc[0][0] += a0 * bv0; acc[0][1] += a0 * bv1; acc[0][2] += a0 * bv2; acc[0][3] += a0 * bv3;
          acc[1][0] += a1 * bv0; acc[1][1] += a1 * bv1; acc[1][2] += a1 * bv2; acc[1][3] += a1 * bv3;
          acc[2][0] += a2 * bv0; acc[2][1] += a2 * bv1; acc[2][2] += a2 * bv2; acc[2][3] += a2 * bv3;
          acc[3][0] += a3 * bv0; acc[3][1] += a3 * bv1; acc[3][2] += a3 * bv2; acc[3][3] += a3 * bv3;
        }
      }
    }
    __syncthreads();
  }

#pragma unroll
  for (int m = 0; m < 4; m++) {
    const int oc = oc0 + j * 4 + m;
    const float bias = b1[oc];
#pragma unroll
    for (int p = 0; p < 4; p++) {
      const int px = i * 4 + p;
      const int y = by * 8 + (px >> 3);
      const int x = bx * 8 + (px & 7);
      float v = acc[m][p] + bias;
      v = v > 0.f ? v : 0.f;
      g_x[(size_t)oc * NPIX + y * WW + x] = v;
    }
  }
}

// ---------------- head: fused 1x1 convs (18 cls + 36 loc), writes transposed into d_out ----------------
__global__ __launch_bounds__(160) void head_kernel(
    const float* __restrict__ wc, const float* __restrict__ bc,
    const float* __restrict__ wl, const float* __restrict__ bl,
    float* __restrict__ out) {
  __shared__ float Xs[32][160];
  __shared__ float Ws[32][54];
  const int tid = threadIdx.x;
  const int px0 = blockIdx.x * 160;

  float acc[54];
#pragma unroll
  for (int o = 0; o < 54; o++) acc[o] = 0.f;

  for (int ic0 = 0; ic0 < 512; ic0 += 32) {
#pragma unroll
    for (int t = 0; t < 32; t++)
      Xs[t][tid] = g_x[(size_t)(ic0 + t) * NPIX + px0 + tid];
    for (int idx = tid; idx < 32 * 54; idx += 160) {
      int ic = idx / 54;
      int o = idx - ic * 54;
      float w = (o < 18) ? wc[o * 512 + ic0 + ic] : wl[(o - 18) * 512 + ic0 + ic];
      Ws[ic][o] = w;
    }
    __syncthreads();
#pragma unroll 4
    for (int ic = 0; ic < 32; ic++) {
      float xv = Xs[ic][tid];
#pragma unroll
      for (int o = 0; o < 54; o++) acc[o] += Ws[ic][o] * xv;
    }
    __syncthreads();
  }

  const int px = px0 + tid;
#pragma unroll
  for (int o = 0; o < 54; o++) {
    float v;
    if (o < 18) {
      v = acc[o] + bc[o];
      int a = o >> 1, cc = o & 1;
      out[CLS_OFF + ((size_t)px * 9 + a) * 2 + cc] = v;
    } else {
      int l = o - 18;
      v = acc[o] + bl[l];
      int a = l >> 2, cc = l & 3;
      out[LOC_OFF + ((size_t)px * 9 + a) * 4 + cc] = v;
    }
  }
}

// ---------------- decode + score + sort key ----------------
__global__ void decode_kernel(const float* __restrict__ anchor,
                              const float* __restrict__ out) {
  const int n = blockIdx.x * 256 + threadIdx.x;
  if (n >= NANCH) return;

  const float ax1 = anchor[(size_t)n * 4 + 0];
  const float ay1 = anchor[(size_t)n * 4 + 1];
  const float ax2 = anchor[(size_t)n * 4 + 2];
  const float ay2 = anchor[(size_t)n * 4 + 3];
  const float acx = __fmul_rn(__fadd_rn(ax2, ax1), 0.5f);
  const float acy = __fmul_rn(__fadd_rn(ay2, ay1), 0.5f);
  const float aw = __fsub_rn(ax2, ax1);
  const float ah = __fsub_rn(ay2, ay1);

  const float l0 = out[LOC_OFF + (size_t)n * 4 + 0];
  const float l1 = out[LOC_OFF + (size_t)n * 4 + 1];
  const float l2 = out[LOC_OFF + (size_t)n * 4 + 2];
  const float l3 = out[LOC_OFF + (size_t)n * 4 + 3];

  const float cx = __fadd_rn(__fmul_rn(l0, aw), acx);
  const float cy = __fadd_rn(__fmul_rn(l1, ah), acy);
  const float w = __fmul_rn(expf(l2), aw);
  const float h = __fmul_rn(expf(l3), ah);

  float x1 = __fsub_rn(cx, __fmul_rn(w, 0.5f));
  float y1 = __fsub_rn(cy, __fmul_rn(h, 0.5f));
  float x2 = __fadd_rn(cx, __fmul_rn(w, 0.5f));
  float y2 = __fadd_rn(cy, __fmul_rn(h, 0.5f));
  x1 = fminf(fmaxf(x1, 0.f), 1.f);
  y1 = fminf(fmaxf(y1, 0.f), 1.f);
  x2 = fminf(fmaxf(x2, 0.f), 1.f);
  y2 = fminf(fmaxf(y2, 0.f), 1.f);

  g_boxes[(size_t)n * 4 + 0] = x1;
  g_boxes[(size_t)n * 4 + 1] = y1;
  g_boxes[(size_t)n * 4 + 2] = x2;
  g_boxes[(size_t)n * 4 + 3] = y2;

  const float c0v = out[CLS_OFF + (size_t)n * 2 + 0];
  const float c1v = out[CLS_OFF + (size_t)n * 2 + 1];
  float s = 1.f / (1.f + expf(__fsub_rn(c0v, c1v)));

  const float MINSZ = (float)(16.0 / 1000.0);
  const float ws = __fsub_rn(x2, x1);
  const float hs = __fsub_rn(y2, y1);
  const bool valid = (hs >= MINSZ) && (ws >= MINSZ);
  if (!valid) s = -1.0f;
  g_score[n] = s;

  unsigned int bits = __float_as_uint(s);
  unsigned int u = (bits & 0x80000000u) ? ~bits : (bits | 0x80000000u);
  // ascending sort -> descending score, ties ascending index (matches jax top_k)
  g_keys[n] = ((unsigned long long)(~u) << 32) | (unsigned int)n;
}

// ---------------- gather top 6000 ----------------
__global__ void gather_kernel() {
  const int i = blockIdx.x * 256 + threadIdx.x;
  if (i >= PRE_NMS) return;
  const unsigned long long k = g_keys_sorted[i];
  const int idx = (int)(k & 0xffffffffu);
  g_top[i * 4 + 0] = g_boxes[(size_t)idx * 4 + 0];
  g_top[i * 4 + 1] = g_boxes[(size_t)idx * 4 + 1];
  g_top[i * 4 + 2] = g_boxes[(size_t)idx * 4 + 2];
  g_top[i * 4 + 3] = g_boxes[(size_t)idx * 4 + 3];
  g_validtop[i] = (g_score[idx] >= 0.f) ? 1 : 0;
}

// ---------------- NMS bitmask ----------------
__global__ __launch_bounds__(64) void mask_kernel() {
  const int cb = blockIdx.x;
  const int rb = blockIdx.y;
  __shared__ float cbx[64][4];
  const int t = threadIdx.x;
  const int jg = cb * 64 + t;
  if (jg < PRE_NMS) {
    cbx[t][0] = g_top[jg * 4 + 0];
    cbx[t][1] = g_top[jg * 4 + 1];
    cbx[t][2] = g_top[jg * 4 + 2];
    cbx[t][3] = g_top[jg * 4 + 3];
  }
  __syncthreads();
  const int i = rb * 64 + t;
  if (i >= PRE_NMS) return;

  const float ix1 = g_top[i * 4 + 0];
  const float iy1 = g_top[i * 4 + 1];
  const float ix2 = g_top[i * 4 + 2];
  const float iy2 = g_top[i * 4 + 3];
  const float area_i = __fmul_rn(__fsub_rn(ix2, ix1), __fsub_rn(iy2, iy1));

  unsigned long long bits = 0ull;
  const int jmax = min(64, PRE_NMS - cb * 64);
  for (int jj = 0; jj < jmax; jj++) {
    const int j = cb * 64 + jj;
    if (j <= i) continue;
    const float bx1 = cbx[jj][0], by1 = cbx[jj][1], bx2 = cbx[jj][2], by2 = cbx[jj][3];
    const float area_j = __fmul_rn(__fsub_rn(bx2, bx1), __fsub_rn(by2, by1));
    const float xx1 = fmaxf(ix1, bx1);
    const float yy1 = fmaxf(iy1, by1);
    const float xx2 = fminf(ix2, bx2);
    const float yy2 = fminf(iy2, by2);
    const float iw = fmaxf(__fsub_rn(xx2, xx1), 0.f);
    const float ih = fmaxf(__fsub_rn(yy2, yy1), 0.f);
    const float inter = __fmul_rn(iw, ih);
    const float denom = __fadd_rn(__fsub_rn(__fadd_rn(area_i, area_j), inter), 1e-12f);
    const float iou = inter / denom;
    if (iou > 0.7f) bits |= (1ull << jj);
  }
  g_mask[(size_t)i * NBLK + cb] = bits;
}

// ---------------- sequential keep (1 warp) + rois write, early exit at 300 ----------------
__global__ void keep_kernel(float* __restrict__ out) {
  const int lane = threadIdx.x;
  unsigned long long r0 = 0ull, r1 = 0ull, r2 = 0ull;  // words lane, lane+32, lane+64
  __shared__ int kept_s[POST_NMS];
  int count = 0;

  for (int i = 0; i < PRE_NMS; i++) {
    const int w = i >> 6;
    const int b = i & 63;
    const int slot = w >> 5;
    const int src = w & 31;
    unsigned long long v = (slot == 0) ? r0 : ((slot == 1) ? r1 : r2);
    unsigned long long wv = __shfl_sync(0xffffffffu, v, src);
    const bool alive = g_validtop[i] && !((wv >> b) & 1ull);
    if (alive) {
      const unsigned long long* row = &g_mask[(size_t)i * NBLK];
      r0 |= row[lane];
      r1 |= row[lane + 32];
      if (lane + 64 < NBLK) r2 |= row[lane + 64];
      if (lane == 0) kept_s[count] = i;
      count++;
      if (count == POST_NMS) break;
    }
  }
  __syncwarp();

  for (int k = lane; k < POST_NMS; k += 32) {
    float b0 = 0.f, b1v = 0.f, b2 = 0.f, b3 = 0.f;
    if (k < count) {
      const int i = kept_s[k];
      b0 = g_top[i * 4 + 0];
      b1v = g_top[i * 4 + 1];
      b2 = g_top[i * 4 + 2];
      b3 = g_top[i * 4 + 3];
    }
    out[ROI_OFF + k * 4 + 0] = b0;
    out[ROI_OFF + k * 4 + 1] = b1v;
    out[ROI_OFF + k * 4 + 2] = b2;
    out[ROI_OFF + k * 4 + 3] = b3;
  }
}

// ---------------- launch ----------------
extern "C" void kernel_launch(void* const* d_in, const int* in_sizes, int n_in,
                              void* d_out, int out_size) {
  const float* feat = (const float*)d_in[0];
  const float* anchor = (const float*)d_in[1];
  const float* w1 = (const float*)d_in[2];
  const float* b1 = (const float*)d_in[3];
  const float* wc = (const float*)d_in[4];
  const float* bc = (const float*)d_in[5];
  const float* wl = (const float*)d_in[6];
  const float* bl = (const float*)d_in[7];
  float* out = (float*)d_out;

  conv1_kernel<<<dim3(25, 25, 8), 256>>>(feat, w1, b1);
  head_kernel<<<250, 160>>>(wc, bc, wl, bl, out);
  decode_kernel<<<(NANCH + 255) / 256, 256>>>(anchor, out);

  // CUB radix sort on 64-bit keys (static temp storage; kernel launches only -> capturable)
  void* d_temp = nullptr;
  unsigned long long* dk = nullptr;
  unsigned long long* dks = nullptr;
  cudaGetSymbolAddress(&d_temp, g_cub_temp);
  cudaGetSymbolAddress((void**)&dk, g_keys);
  cudaGetSymbolAddress((void**)&dks, g_keys_sorted);
  size_t temp_bytes = 0;
  cub::DeviceRadixSort::SortKeys(nullptr, temp_bytes, dk, dks, NANCH, 0, 64,
                                 (cudaStream_t)0);
  if (temp_bytes > (size_t)(64u << 20)) temp_bytes = (size_t)(64u << 20);
  cub::DeviceRadixSort::SortKeys(d_temp, temp_bytes, dk, dks, NANCH, 0, 64,
                                 (cudaStream_t)0);

  gather_kernel<<<(PRE_NMS + 255) / 256, 256>>>();
  mask_kernel<<<dim3(NBLK, NBLK), 64>>>();
  keep_kernel<<<1, 32>>>(out);
}